// round 8
// baseline (speedup 1.0000x reference)
#include <cuda_runtime.h>
#include <cuda_fp16.h>
#include <cuda_bf16.h>
#include <cstdint>

// y[16,8192] = x[16,8192] @ dequant_q8_0(W)[8192,8192]^T + bias[8192]
// Q8_0 block: 2-byte fp16 scale + 32 int8 -> 34 "bytes"; 256 blocks/row.
// quantized_weight arrives WIDENED to an unknown dtype (probed at runtime);
// all loaders are mode-templated and consume the widened buffer directly.

#define IN_F      8192
#define OUT_F     8192
#define BATCH     16
#define ROW_ELEMS 8704
#define NSPLIT    8
#define BLOCKS_PER_SPLIT 32     // 256 k-blocks / 8
#define KSPLIT    1024

__device__ int    g_mode;
__device__ __half g_x16[BATCH * IN_F];                 // 256 KB
__device__ float  g_partial[NSPLIT][BATCH][OUT_F];     // 4 MB

// ---------------------------------------------------------------------------
// Kernel 1: convert x to f16 (blocks 0..127, float4-vectorized) + probe (block 128)
//   mode 0: raw bytes  1: int32  2: float32  3: bfloat16  4: float16
// ---------------------------------------------------------------------------
__global__ void convert_probe_kernel(const float* __restrict__ x,
                                     const uint32_t* __restrict__ qw) {
    if (blockIdx.x < 128) {
        int i4 = blockIdx.x * 256 + threadIdx.x;        // float4 index
        float4 v = *reinterpret_cast<const float4*>(x + i4 * 4);
        __half2 h0 = __floats2half2_rn(v.x, v.y);
        __half2 h1 = __floats2half2_rn(v.z, v.w);
        uint2 w;
        w.x = *reinterpret_cast<uint32_t*>(&h0);
        w.y = *reinterpret_cast<uint32_t*>(&h1);
        *reinterpret_cast<uint2*>(&g_x16[i4 * 4]) = w;
        return;
    }
    __shared__ int ok[4];   // i32, f32, bf16, f16
    int t = threadIdx.x;
    if (t < 4) ok[t] = 1;
    __syncthreads();
    for (int i = t; i < 4096; i += blockDim.x) {
        uint32_t w = qw[i];
        if (w > 255u) ok[0] = 0;
        float f = __uint_as_float(w);
        if (!(f >= 0.f && f <= 255.f && f == floorf(f))) ok[1] = 0;
        float b0 = __bfloat162float(__ushort_as_bfloat16((uint16_t)(w & 0xFFFFu)));
        float b1 = __bfloat162float(__ushort_as_bfloat16((uint16_t)(w >> 16)));
        if (!(b0 >= 0.f && b0 <= 255.f && b0 == floorf(b0) &&
              b1 >= 0.f && b1 <= 255.f && b1 == floorf(b1))) ok[2] = 0;
        float h0 = __half2float(__ushort_as_half((uint16_t)(w & 0xFFFFu)));
        float h1 = __half2float(__ushort_as_half((uint16_t)(w >> 16)));
        if (!(h0 >= 0.f && h0 <= 255.f && h0 == floorf(h0) &&
              h1 >= 0.f && h1 <= 255.f && h1 == floorf(h1))) ok[3] = 0;
    }
    __syncthreads();
    if (t == 0) {
        int m = 0;
        if (ok[0]) m = 1;
        else if (ok[1]) m = 2;
        else if (ok[2]) m = 3;
        else if (ok[3]) m = 4;
        g_mode = m;
    }
}

// ---------------------------------------------------------------------------
// Raw (pre-pack) load containers: loads issue at fetch, ALU deferred to pack.
// ---------------------------------------------------------------------------
template<int M> struct QRaw { uint32_t w[(M == 0) ? 1 : ((M <= 2) ? 4 : 2)]; };
template<int M> struct SRaw { uint32_t w[(M == 0) ? 1 : ((M <= 2) ? 2 : 1)]; };

// quant bytes {e, e+1, e+8, e+9} of the GGML stream
template<int M>
__device__ __forceinline__ QRaw<M> fetch_q4(const uint8_t* __restrict__ p, size_t e) {
    QRaw<M> r;
    if constexpr (M == 0) {
        uint32_t lo = *reinterpret_cast<const uint16_t*>(p + e);
        uint32_t hi = *reinterpret_cast<const uint16_t*>(p + e + 8);
        r.w[0] = lo | (hi << 16);
    } else if constexpr (M == 1 || M == 2) {
        uint2 a = *reinterpret_cast<const uint2*>(p + e * 4);
        uint2 b = *reinterpret_cast<const uint2*>(p + (e + 8) * 4);
        r.w[0] = a.x; r.w[1] = a.y; r.w[2] = b.x; r.w[3] = b.y;
    } else {
        r.w[0] = *reinterpret_cast<const uint32_t*>(p + e * 2);
        r.w[1] = *reinterpret_cast<const uint32_t*>(p + (e + 8) * 2);
    }
    return r;
}

template<int M>
__device__ __forceinline__ uint32_t pack_q4(QRaw<M> r) {
    if constexpr (M == 0) {
        return r.w[0];
    } else if constexpr (M == 1) {
        return (r.w[0] & 0xFFu) | ((r.w[1] & 0xFFu) << 8)
             | ((r.w[2] & 0xFFu) << 16) | ((r.w[3] & 0xFFu) << 24);
    } else if constexpr (M == 2) {
        return ((uint32_t)(int)__uint_as_float(r.w[0]) & 0xFFu)
             | (((uint32_t)(int)__uint_as_float(r.w[1]) & 0xFFu) << 8)
             | (((uint32_t)(int)__uint_as_float(r.w[2]) & 0xFFu) << 16)
             | (((uint32_t)(int)__uint_as_float(r.w[3]) & 0xFFu) << 24);
    } else if constexpr (M == 3) {
        uint32_t b0 = (uint32_t)(int)__bfloat162float(__ushort_as_bfloat16((uint16_t)(r.w[0] & 0xFFFFu))) & 0xFFu;
        uint32_t b1 = (uint32_t)(int)__bfloat162float(__ushort_as_bfloat16((uint16_t)(r.w[0] >> 16)))     & 0xFFu;
        uint32_t b2 = (uint32_t)(int)__bfloat162float(__ushort_as_bfloat16((uint16_t)(r.w[1] & 0xFFFFu))) & 0xFFu;
        uint32_t b3 = (uint32_t)(int)__bfloat162float(__ushort_as_bfloat16((uint16_t)(r.w[1] >> 16)))     & 0xFFu;
        return b0 | (b1 << 8) | (b2 << 16) | (b3 << 24);
    } else {
        uint32_t b0 = (uint32_t)(int)__half2float(__ushort_as_half((uint16_t)(r.w[0] & 0xFFFFu))) & 0xFFu;
        uint32_t b1 = (uint32_t)(int)__half2float(__ushort_as_half((uint16_t)(r.w[0] >> 16)))     & 0xFFu;
        uint32_t b2 = (uint32_t)(int)__half2float(__ushort_as_half((uint16_t)(r.w[1] & 0xFFFFu))) & 0xFFu;
        uint32_t b3 = (uint32_t)(int)__half2float(__ushort_as_half((uint16_t)(r.w[1] >> 16)))     & 0xFFu;
        return b0 | (b1 << 8) | (b2 << 16) | (b3 << 24);
    }
}

// fp16 scale bytes {e, e+1}
template<int M>
__device__ __forceinline__ SRaw<M> fetch_sc(const uint8_t* __restrict__ p, size_t e) {
    SRaw<M> r;
    if constexpr (M == 0) {
        r.w[0] = *reinterpret_cast<const uint16_t*>(p + e);
    } else if constexpr (M == 1 || M == 2) {
        uint2 a = *reinterpret_cast<const uint2*>(p + e * 4);
        r.w[0] = a.x; r.w[1] = a.y;
    } else {
        r.w[0] = *reinterpret_cast<const uint32_t*>(p + e * 2);
    }
    return r;
}

template<int M>
__device__ __forceinline__ float pack_sc(SRaw<M> r) {
    uint16_t bits;
    if constexpr (M == 0) {
        bits = (uint16_t)r.w[0];
    } else if constexpr (M == 1) {
        bits = (uint16_t)((r.w[0] & 0xFFu) | ((r.w[1] & 0xFFu) << 8));
    } else if constexpr (M == 2) {
        bits = (uint16_t)(((int)__uint_as_float(r.w[0]) & 0xFF)
                        | (((int)__uint_as_float(r.w[1]) & 0xFF) << 8));
    } else if constexpr (M == 3) {
        bits = (uint16_t)(((int)__bfloat162float(__ushort_as_bfloat16((uint16_t)(r.w[0] & 0xFFFFu))) & 0xFF)
                        | (((int)__bfloat162float(__ushort_as_bfloat16((uint16_t)(r.w[0] >> 16))) & 0xFF) << 8));
    } else {
        bits = (uint16_t)(((int)__half2float(__ushort_as_half((uint16_t)(r.w[0] & 0xFFFFu))) & 0xFF)
                        | (((int)__half2float(__ushort_as_half((uint16_t)(r.w[0] >> 16))) & 0xFF) << 8));
    }
    return __half2float(__ushort_as_half(bits));
}

// ---------------------------------------------------------------------------
__device__ __forceinline__ void mma16816(float c[4], const uint32_t a[4],
                                         uint32_t b0, uint32_t b1) {
    asm volatile(
        "mma.sync.aligned.m16n8k16.row.col.f32.f16.f16.f32 "
        "{%0,%1,%2,%3}, {%4,%5,%6,%7}, {%8,%9}, {%0,%1,%2,%3};\n"
        : "+f"(c[0]), "+f"(c[1]), "+f"(c[2]), "+f"(c[3])
        : "r"(a[0]), "r"(a[1]), "r"(a[2]), "r"(a[3]), "r"(b0), "r"(b1));
}

// u32 {k,k+1,k+8,k+9} int8 -> two f16x2 regs with EXACT integer q values.
__device__ __forceinline__ void make_bfrag(uint32_t u, uint32_t& w0, uint32_t& w1) {
    u ^= 0x80808080u;
    uint32_t r0 = __byte_perm(u, 0x64646464u, 0x4140);
    uint32_t r1 = __byte_perm(u, 0x64646464u, 0x4342);
    const __half2 magic = __halves2half2(__ushort_as_half(0x6480),
                                         __ushort_as_half(0x6480));   // 1152.0
    __half2 h0 = __hsub2(*reinterpret_cast<__half2*>(&r0), magic);
    __half2 h1 = __hsub2(*reinterpret_cast<__half2*>(&r1), magic);
    w0 = *reinterpret_cast<uint32_t*>(&h0);
    w1 = *reinterpret_cast<uint32_t*>(&h1);
}

// ---------------------------------------------------------------------------
// Pipelined stage: all raw loads for one k-block (quants, scales, A-frags).
// ---------------------------------------------------------------------------
template<int M> struct Stage {
    QRaw<M> q[4];      // {tile0,kin0},{tile1,kin0},{tile0,kin16},{tile1,kin16}
    SRaw<M> s[4];      // scales for cols n0+2t, +1, n0+8+2t, +1
    uint32_t a[8];     // A frags: kin0 x4, kin16 x4
};

struct Ctx {
    const uint8_t* qw;
    size_t rq0, rq1, rs0, rs1, rs2, rs3;   // row bases (GGML elements)
    const __half* xr0;
    const __half* xr1;
    int t;
};

template<int M>
__device__ __forceinline__ void fetch_stage(Stage<M>& st, const Ctx& c, int blk) {
    const size_t boff = (size_t)blk * 34;
    const size_t qo = boff + 2 + 2 * c.t;
    st.q[0] = fetch_q4<M>(c.qw, c.rq0 + qo);
    st.q[1] = fetch_q4<M>(c.qw, c.rq1 + qo);
    st.q[2] = fetch_q4<M>(c.qw, c.rq0 + qo + 16);
    st.q[3] = fetch_q4<M>(c.qw, c.rq1 + qo + 16);
    st.s[0] = fetch_sc<M>(c.qw, c.rs0 + boff);
    st.s[1] = fetch_sc<M>(c.qw, c.rs1 + boff);
    st.s[2] = fetch_sc<M>(c.qw, c.rs2 + boff);
    st.s[3] = fetch_sc<M>(c.qw, c.rs3 + boff);
    const int kbase = blk * 32;
    const __half* p0 = c.xr0 + kbase;
    const __half* p1 = c.xr1 + kbase;
    st.a[0] = *reinterpret_cast<const uint32_t*>(p0);
    st.a[1] = *reinterpret_cast<const uint32_t*>(p1);
    st.a[2] = *reinterpret_cast<const uint32_t*>(p0 + 8);
    st.a[3] = *reinterpret_cast<const uint32_t*>(p1 + 8);
    st.a[4] = *reinterpret_cast<const uint32_t*>(p0 + 16);
    st.a[5] = *reinterpret_cast<const uint32_t*>(p1 + 16);
    st.a[6] = *reinterpret_cast<const uint32_t*>(p0 + 24);
    st.a[7] = *reinterpret_cast<const uint32_t*>(p1 + 24);
}

template<int M>
__device__ __forceinline__ void compute_stage(const Stage<M>& st,
                                              float c0[4], float c1[4]) {
    float cb0[4] = {0.f, 0.f, 0.f, 0.f};
    float cb1[4] = {0.f, 0.f, 0.f, 0.f};
    uint32_t w0, w1;
    make_bfrag(pack_q4<M>(st.q[0]), w0, w1); mma16816(cb0, st.a,     w0, w1);
    make_bfrag(pack_q4<M>(st.q[1]), w0, w1); mma16816(cb1, st.a,     w0, w1);
    make_bfrag(pack_q4<M>(st.q[2]), w0, w1); mma16816(cb0, st.a + 4, w0, w1);
    make_bfrag(pack_q4<M>(st.q[3]), w0, w1); mma16816(cb1, st.a + 4, w0, w1);
    const float d0 = pack_sc<M>(st.s[0]);
    const float d1 = pack_sc<M>(st.s[1]);
    const float d2 = pack_sc<M>(st.s[2]);
    const float d3 = pack_sc<M>(st.s[3]);
    c0[0] = fmaf(d0, cb0[0], c0[0]);
    c0[1] = fmaf(d1, cb0[1], c0[1]);
    c0[2] = fmaf(d0, cb0[2], c0[2]);
    c0[3] = fmaf(d1, cb0[3], c0[3]);
    c1[0] = fmaf(d2, cb1[0], c1[0]);
    c1[1] = fmaf(d3, cb1[1], c1[1]);
    c1[2] = fmaf(d2, cb1[2], c1[2]);
    c1[3] = fmaf(d3, cb1[3], c1[3]);
}

// ---------------------------------------------------------------------------
// GEMM: grid (128 col-tiles, 8 k-splits), 128 threads (4 warps, 16 cols each).
// ---------------------------------------------------------------------------
template<int M>
__device__ __forceinline__ void gemm_body(const uint8_t* __restrict__ qw) {
    const int warp = threadIdx.x >> 5;
    const int lane = threadIdx.x & 31;
    const int g = lane >> 2;
    const int t = lane & 3;
    const int s = blockIdx.y;
    const int n0 = blockIdx.x * 64 + warp * 16;

    Ctx c;
    c.qw  = qw;
    c.t   = t;
    c.rq0 = (size_t)(n0 + g) * ROW_ELEMS;
    c.rq1 = (size_t)(n0 + 8 + g) * ROW_ELEMS;
    c.rs0 = (size_t)(n0 + 2 * t) * ROW_ELEMS;
    c.rs1 = c.rs0 + ROW_ELEMS;
    c.rs2 = (size_t)(n0 + 8 + 2 * t) * ROW_ELEMS;
    c.rs3 = c.rs2 + ROW_ELEMS;
    c.xr0 = g_x16 + g * IN_F + 2 * t;
    c.xr1 = c.xr0 + 8 * IN_F;

    const int blk_begin = s * BLOCKS_PER_SPLIT;
    const int blk_end   = blk_begin + BLOCKS_PER_SPLIT;

    float c0[4] = {0.f, 0.f, 0.f, 0.f};
    float c1[4] = {0.f, 0.f, 0.f, 0.f};

    Stage<M> sA, sB;
    fetch_stage<M>(sA, c, blk_begin);

    #pragma unroll 1
    for (int blk = blk_begin; blk < blk_end; blk += 2) {
        fetch_stage<M>(sB, c, blk + 1);            // in flight during compute(sA)
        compute_stage<M>(sA, c0, c1);
        if (blk + 2 < blk_end)
            fetch_stage<M>(sA, c, blk + 2);        // in flight during compute(sB)
        compute_stage<M>(sB, c0, c1);
    }

    int col = n0 + 2 * t;
    *reinterpret_cast<float2*>(&g_partial[s][g][col])     = make_float2(c0[0], c0[1]);
    *reinterpret_cast<float2*>(&g_partial[s][g + 8][col]) = make_float2(c0[2], c0[3]);
    col += 8;
    *reinterpret_cast<float2*>(&g_partial[s][g][col])     = make_float2(c1[0], c1[1]);
    *reinterpret_cast<float2*>(&g_partial[s][g + 8][col]) = make_float2(c1[2], c1[3]);
}

__global__ __launch_bounds__(128) void gemm_kernel(const uint8_t* __restrict__ qw) {
    const int mode = g_mode;      // uniform
    if      (mode == 1) gemm_body<1>(qw);
    else if (mode == 2) gemm_body<2>(qw);
    else if (mode == 0) gemm_body<0>(qw);
    else if (mode == 3) gemm_body<3>(qw);
    else                gemm_body<4>(qw);
}

// ---------------------------------------------------------------------------
// split-K reduce + bias (deterministic, float4)
// ---------------------------------------------------------------------------
__global__ void reduce_kernel(const float* __restrict__ bias, float* __restrict__ out) {
    int i4 = blockIdx.x * blockDim.x + threadIdx.x;
    if (i4 >= (BATCH * OUT_F) / 4) return;
    int i = i4 * 4;
    int n = i & (OUT_F - 1);
    const float* p = &g_partial[0][0][0];
    float4 v = *reinterpret_cast<const float4*>(bias + n);
    #pragma unroll
    for (int s = 0; s < NSPLIT; ++s) {
        float4 a = *reinterpret_cast<const float4*>(p + i + s * BATCH * OUT_F);
        v.x += a.x; v.y += a.y; v.z += a.z; v.w += a.w;
    }
    *reinterpret_cast<float4*>(out + i) = v;
}

// ---------------------------------------------------------------------------
extern "C" void kernel_launch(void* const* d_in, const int* in_sizes, int n_in,
                              void* d_out, int out_size) {
    // Inputs by SIZE RANK (units-agnostic): qw (largest) > x (middle) > bias.
    int iq = 0, ix = 0, ib = 0;
    for (int i = 1; i < n_in; ++i) if (in_sizes[i] > in_sizes[iq]) iq = i;
    ib = (iq == 0) ? 1 : 0;
    for (int i = 0; i < n_in; ++i)
        if (i != iq && in_sizes[i] < in_sizes[ib]) ib = i;
    for (int i = 0; i < n_in; ++i)
        if (i != iq && i != ib) { ix = i; break; }

    const uint8_t* qw   = (const uint8_t*)d_in[iq];
    const float*   x    = (const float*)d_in[ix];
    const float*   bias = (const float*)d_in[ib];
    float* out = (float*)d_out;

    convert_probe_kernel<<<129, 256>>>(x, (const uint32_t*)qw);
    gemm_kernel<<<dim3(OUT_F / 64, NSPLIT), 128>>>(qw);
    reduce_kernel<<<(BATCH * OUT_F / 4 + 255) / 256, 256>>>(bias, out);
}